// round 6
// baseline (speedup 1.0000x reference)
#include <cuda_runtime.h>
#include <cuda_fp16.h>

#define NUP1    100001            // NUM_USERS + 1
#define NROWS   200001            // total nodes
#define NNZE    2000000
#define NNZ_PAD 3400064           // nnz + 7*NROWS upper bound (pad to mult of 8)
#define NF2     (NROWS * 32)      // 32 x (float2|half2) per node = 64 scalars
#define SCAN_B  1024
#define NB      ((NROWS + SCAN_B - 1) / SCAN_B)   // 196

// ---- static device scratch (zero-initialized at load; pad slots never written) ----
__device__ float2  g_A  [NF2];    // layer 0, fp32 (exact dominant term)
__device__ __half2 g_A16[NF2];    // fp16 mirror of layer 0
__device__ __half2 g_B16[NF2];    // layer 1 output
__device__ __half2 g_C16[NF2];    // layer 2 output

__device__ int   g_cnt[NROWS];
__device__ int   g_ptr[NROWS + 1];
__device__ int   g_fill[NROWS];
__device__ uint2 g_edge[NNZ_PAD];            // (col, fp32 val bits); pad = (0,0)
__device__ volatile unsigned long long g_look[NB];  // lookback: (state<<32)|value

// init embeddings + zero cnt + zero lookback state
__global__ void init_kernel(const float2* __restrict__ user2,
                            const float2* __restrict__ item2) {
    int i = blockIdx.x * blockDim.x + threadIdx.x;
    if (i < NB)    g_look[i] = 0ull;
    if (i < NROWS) g_cnt[i] = 0;
    if (i >= NF2) return;
    float2 v = (i < NUP1 * 32) ? __ldg(&user2[i])
                               : __ldg(&item2[i - NUP1 * 32 + 32]);
    g_A[i]   = v;
    g_A16[i] = __float22half2_rn(v);
}

__global__ void hist_kernel(const int* __restrict__ rows, int nnz) {
    int e = blockIdx.x * blockDim.x + threadIdx.x;
    if (e < nnz) atomicAdd(&g_cnt[rows[e]], 1);
}

// Single-pass decoupled-lookback scan over PADDED counts -> g_ptr / g_fill.
__global__ void scan_kernel() {
    int t = threadIdx.x, b = blockIdx.x;
    int lane = t & 31, wid = t >> 5;
    int gid = b * SCAN_B + t;

    int cnt = (gid < NROWS) ? g_cnt[gid] : 0;
    int pc  = (cnt + 7) & ~7;                 // padded count

    // warp inclusive scan
    int incl = pc;
    #pragma unroll
    for (int o = 1; o < 32; o <<= 1) {
        int n = __shfl_up_sync(0xffffffffu, incl, o);
        if (lane >= o) incl += n;
    }
    __shared__ int wsum[32];
    __shared__ int s_excl;
    if (lane == 31) wsum[wid] = incl;
    __syncthreads();
    if (wid == 0) {
        int v = wsum[lane];
        #pragma unroll
        for (int o = 1; o < 32; o <<= 1) {
            int n = __shfl_up_sync(0xffffffffu, v, o);
            if (lane >= o) v += n;
        }
        wsum[lane] = v;
    }
    __syncthreads();
    int block_incl = incl + (wid ? wsum[wid - 1] : 0);
    int total = wsum[31];

    if (t == 0) {
        if (b == 0) { g_look[0] = (2ull << 32) | (unsigned)total; s_excl = 0; }
        else          g_look[b] = (1ull << 32) | (unsigned)total;
    }
    if (b > 0 && wid == 0) {
        int excl = 0;
        int idx = b - 1;
        while (true) {
            int look = idx - lane;
            unsigned long long w; int st;
            do {
                w = g_look[look < 0 ? 0 : look];
                st = (look < 0) ? 2 : (int)(w >> 32);
            } while (__any_sync(0xffffffffu, st == 0));
            int val = (look < 0) ? 0 : (int)(unsigned)w;
            unsigned pm = __ballot_sync(0xffffffffu, (look >= 0) && st == 2);
            int contrib;
            if (pm) {
                int plane = __ffs(pm) - 1;          // nearest prefix lane
                contrib = (lane <= plane) ? val : 0;
            } else {
                contrib = val;
            }
            #pragma unroll
            for (int o = 16; o; o >>= 1)
                contrib += __shfl_down_sync(0xffffffffu, contrib, o);
            contrib = __shfl_sync(0xffffffffu, contrib, 0);
            excl += contrib;
            if (pm) break;
            idx -= 32;
        }
        if (lane == 0) {
            g_look[b] = (2ull << 32) | (unsigned)(excl + total);
            s_excl = excl;
        }
    }
    __syncthreads();
    if (gid < NROWS) {
        int ex = s_excl + block_incl - pc;
        g_ptr[gid]  = ex;
        g_fill[gid] = ex;
        if (gid == NROWS - 1) g_ptr[NROWS] = ex + pc;
    }
}

__global__ void scatter_kernel(const int* __restrict__ rows,
                               const int* __restrict__ cols,
                               const float* __restrict__ vals, int nnz) {
    int e = blockIdx.x * blockDim.x + threadIdx.x;
    if (e >= nnz) return;
    int r = rows[e];
    int pos = atomicAdd(&g_fill[r], 1);
    g_edge[pos] = make_uint2((unsigned)cols[e], (unsigned)__float_as_int(vals[e]));
}

// One warp per row; branchless 8-wide unrolled loop; edge loads are
// warp-uniform broadcasts (no SHFL chain). Pad edges are (0, 0.0f).
__device__ __forceinline__ float2 row_spmv16(const __half2* __restrict__ x,
                                             int s, int e, int lane) {
    float2 sum = make_float2(0.f, 0.f);
    for (int j = s; j < e; j += 8) {
        uint2 e0 = __ldg(&g_edge[j + 0]);
        uint2 e1 = __ldg(&g_edge[j + 1]);
        uint2 e2 = __ldg(&g_edge[j + 2]);
        uint2 e3 = __ldg(&g_edge[j + 3]);
        uint2 e4 = __ldg(&g_edge[j + 4]);
        uint2 e5 = __ldg(&g_edge[j + 5]);
        uint2 e6 = __ldg(&g_edge[j + 6]);
        uint2 e7 = __ldg(&g_edge[j + 7]);
        __half2 h0 = __ldg(&x[(int)e0.x * 32 + lane]);
        __half2 h1 = __ldg(&x[(int)e1.x * 32 + lane]);
        __half2 h2 = __ldg(&x[(int)e2.x * 32 + lane]);
        __half2 h3 = __ldg(&x[(int)e3.x * 32 + lane]);
        __half2 h4 = __ldg(&x[(int)e4.x * 32 + lane]);
        __half2 h5 = __ldg(&x[(int)e5.x * 32 + lane]);
        __half2 h6 = __ldg(&x[(int)e6.x * 32 + lane]);
        __half2 h7 = __ldg(&x[(int)e7.x * 32 + lane]);
        float2 x0 = __half22float2(h0);
        float2 x1 = __half22float2(h1);
        float2 x2 = __half22float2(h2);
        float2 x3 = __half22float2(h3);
        float2 x4 = __half22float2(h4);
        float2 x5 = __half22float2(h5);
        float2 x6 = __half22float2(h6);
        float2 x7 = __half22float2(h7);
        float v0 = __int_as_float((int)e0.y);
        float v1 = __int_as_float((int)e1.y);
        float v2 = __int_as_float((int)e2.y);
        float v3 = __int_as_float((int)e3.y);
        float v4 = __int_as_float((int)e4.y);
        float v5 = __int_as_float((int)e5.y);
        float v6 = __int_as_float((int)e6.y);
        float v7 = __int_as_float((int)e7.y);
        sum.x = fmaf(v0, x0.x, sum.x);  sum.y = fmaf(v0, x0.y, sum.y);
        sum.x = fmaf(v1, x1.x, sum.x);  sum.y = fmaf(v1, x1.y, sum.y);
        sum.x = fmaf(v2, x2.x, sum.x);  sum.y = fmaf(v2, x2.y, sum.y);
        sum.x = fmaf(v3, x3.x, sum.x);  sum.y = fmaf(v3, x3.y, sum.y);
        sum.x = fmaf(v4, x4.x, sum.x);  sum.y = fmaf(v4, x4.y, sum.y);
        sum.x = fmaf(v5, x5.x, sum.x);  sum.y = fmaf(v5, x5.y, sum.y);
        sum.x = fmaf(v6, x6.x, sum.x);  sum.y = fmaf(v6, x6.y, sum.y);
        sum.x = fmaf(v7, x7.x, sum.x);  sum.y = fmaf(v7, x7.y, sum.y);
    }
    return sum;
}

__global__ void spmm_mid(int layer) {
    int warp = (blockIdx.x * blockDim.x + threadIdx.x) >> 5;
    int lane = threadIdx.x & 31;
    if (warp >= NROWS) return;
    const __half2* __restrict__ x = (layer == 0) ? g_A16 : g_B16;
    __half2*       __restrict__ y = (layer == 0) ? g_B16 : g_C16;
    float2 sum = row_spmv16(x, g_ptr[warp], g_ptr[warp + 1], lane);
    y[warp * 32 + lane] = __float22half2_rn(sum);
}

__global__ void spmm_final(float2* __restrict__ out) {
    int warp = (blockIdx.x * blockDim.x + threadIdx.x) >> 5;
    int lane = threadIdx.x & 31;
    if (warp >= NROWS) return;
    float2 sum = row_spmv16(g_C16, g_ptr[warp], g_ptr[warp + 1], lane);
    int o = warp * 32 + lane;
    float2 a = g_A[o];
    float2 b = __half22float2(g_B16[o]);
    float2 c = __half22float2(g_C16[o]);
    int outrow = (warp < NUP1) ? warp : warp + 1;
    out[(size_t)outrow * 32 + lane] =
        make_float2((a.x + b.x + c.x + sum.x) * 0.25f,
                    (a.y + b.y + c.y + sum.y) * 0.25f);
    if (warp == 0)
        out[(size_t)NUP1 * 32 + lane] = make_float2(0.f, 0.f);
}

extern "C" void kernel_launch(void* const* d_in, const int* in_sizes, int n_in,
                              void* d_out, int out_size) {
    const float2* user2 = (const float2*)d_in[0];
    const float2* item2 = (const float2*)d_in[1];
    const int*    rows  = (const int*)d_in[2];
    const int*    cols  = (const int*)d_in[3];
    const float*  vals  = (const float*)d_in[4];
    float2*       out   = (float2*)d_out;

    const int nnz = in_sizes[2];
    const int TB = 256;

    const int gInit = (NF2 + TB - 1) / TB;
    const int gEdge = (nnz + TB - 1) / TB;
    const int gSpmm = (NROWS * 32 + TB - 1) / TB;

    init_kernel<<<gInit, TB>>>(user2, item2);        // 1
    hist_kernel<<<gEdge, TB>>>(rows, nnz);           // 2
    scan_kernel<<<NB, SCAN_B>>>();                   // 3 (single-pass lookback)
    scatter_kernel<<<gEdge, TB>>>(rows, cols, vals, nnz); // 4
    spmm_mid<<<gSpmm, TB>>>(0);                      // 5: A16 -> B16
    spmm_mid<<<gSpmm, TB>>>(1);                      // 6: B16 -> C16  (ncu lands here)
    spmm_final<<<gSpmm, TB>>>(out);                  // 7
}

// round 7
// speedup vs baseline: 1.2828x; 1.2828x over previous
#include <cuda_runtime.h>
#include <cuda_fp16.h>

#define NUP1    100001            // NUM_USERS + 1
#define NROWS   200001            // total nodes
#define NNZE    2000000
#define NF4     (NROWS * 16)      // 16 x (float4|half4) per node = 64 scalars
#define SCAN_B  1024
#define NB      ((NROWS + SCAN_B - 1) / SCAN_B)   // 196

// ---- static device scratch ----
__device__ float4 g_A4 [NF4];     // layer 0 fp32
__device__ uint2  g_A16[NF4];     // layer 0 fp16 (half4 packed)
__device__ uint2  g_B16[NF4];     // layer 1 fp16
__device__ uint2  g_C16[NF4];     // layer 2 fp16

__device__ int   g_cnt[NROWS];    // zero at start of every run (scan self-clears)
__device__ int   g_ptr[NROWS + 1];
__device__ int   g_fill[NROWS];
__device__ uint2 g_edge[NNZE];    // (col, fp32 val bits)
__device__ volatile unsigned long long g_look[NB];  // cleared by scatter

__device__ __forceinline__ uint2 pack_half4(float2 a, float2 b) {
    __half2 h0 = __floats2half2_rn(a.x, a.y);
    __half2 h1 = __floats2half2_rn(b.x, b.y);
    return make_uint2(*(unsigned*)&h0, *(unsigned*)&h1);
}
__device__ __forceinline__ void unpack_half4(uint2 u, float2& a, float2& b) {
    __half2 h0 = *(__half2*)&u.x;
    __half2 h1 = *(__half2*)&u.y;
    a = __half22float2(h0);
    b = __half22float2(h1);
}

// init embeddings (fp32 + fp16 mirror) AND histogram rows (fused).
__global__ void init_kernel(const float4* __restrict__ user4,
                            const float4* __restrict__ item4,
                            const int* __restrict__ rows, int nnz) {
    int i = blockIdx.x * blockDim.x + threadIdx.x;
    if (i < nnz) atomicAdd(&g_cnt[rows[i]], 1);
    if (i >= NF4) return;
    float4 v = (i < NUP1 * 16) ? __ldg(&user4[i])
                               : __ldg(&item4[i - NUP1 * 16 + 16]);
    g_A4[i]  = v;
    g_A16[i] = pack_half4(make_float2(v.x, v.y), make_float2(v.z, v.w));
}

// Single-pass decoupled-lookback scan -> g_ptr/g_fill; self-clears g_cnt.
__global__ void scan_kernel() {
    int t = threadIdx.x, b = blockIdx.x;
    int lane = t & 31, wid = t >> 5;
    int gid = b * SCAN_B + t;

    int cnt = (gid < NROWS) ? g_cnt[gid] : 0;

    int incl = cnt;
    #pragma unroll
    for (int o = 1; o < 32; o <<= 1) {
        int n = __shfl_up_sync(0xffffffffu, incl, o);
        if (lane >= o) incl += n;
    }
    __shared__ int wsum[32];
    __shared__ int s_excl;
    if (lane == 31) wsum[wid] = incl;
    __syncthreads();
    if (wid == 0) {
        int v = wsum[lane];
        #pragma unroll
        for (int o = 1; o < 32; o <<= 1) {
            int n = __shfl_up_sync(0xffffffffu, v, o);
            if (lane >= o) v += n;
        }
        wsum[lane] = v;
    }
    __syncthreads();
    int block_incl = incl + (wid ? wsum[wid - 1] : 0);
    int total = wsum[31];

    if (t == 0) {
        if (b == 0) { g_look[0] = (2ull << 32) | (unsigned)total; s_excl = 0; }
        else          g_look[b] = (1ull << 32) | (unsigned)total;
    }
    if (b > 0 && wid == 0) {
        int excl = 0;
        int idx = b - 1;
        while (true) {
            int look = idx - lane;
            unsigned long long w; int st;
            do {
                w = g_look[look < 0 ? 0 : look];
                st = (look < 0) ? 2 : (int)(w >> 32);
            } while (__any_sync(0xffffffffu, st == 0));
            int val = (look < 0) ? 0 : (int)(unsigned)w;
            unsigned pm = __ballot_sync(0xffffffffu, (look >= 0) && st == 2);
            int contrib;
            if (pm) {
                int plane = __ffs(pm) - 1;
                contrib = (lane <= plane) ? val : 0;
            } else {
                contrib = val;
            }
            #pragma unroll
            for (int o = 16; o; o >>= 1)
                contrib += __shfl_down_sync(0xffffffffu, contrib, o);
            contrib = __shfl_sync(0xffffffffu, contrib, 0);
            excl += contrib;
            if (pm) break;
            idx -= 32;
        }
        if (lane == 0) {
            g_look[b] = (2ull << 32) | (unsigned)(excl + total);
            s_excl = excl;
        }
    }
    __syncthreads();
    if (gid < NROWS) {
        int ex = s_excl + block_incl - cnt;
        g_ptr[gid]  = ex;
        g_fill[gid] = ex;
        g_cnt[gid]  = 0;                       // self-clean for next replay
        if (gid == NROWS - 1) g_ptr[NROWS] = ex + cnt;
    }
}

// Bucket edges; also clears g_look for the next replay.
__global__ void scatter_kernel(const int* __restrict__ rows,
                               const int* __restrict__ cols,
                               const float* __restrict__ vals, int nnz) {
    int e = blockIdx.x * blockDim.x + threadIdx.x;
    if (e < NB) g_look[e] = 0ull;
    if (e >= nnz) return;
    int r = rows[e];
    int pos = atomicAdd(&g_fill[r], 1);
    g_edge[pos] = make_uint2((unsigned)cols[e], (unsigned)__float_as_int(vals[e]));
}

// Half-warp per row: 16 lanes x half4 (8B) = one 128B row.
// 4-way unrolled, per-lane bounds predication (out-of-range -> col 0, val 0).
__device__ __forceinline__ void row_spmv(const uint2* __restrict__ x,
                                         int s, int e, int l15,
                                         float2& s0, float2& s1) {
    s0 = make_float2(0.f, 0.f);
    s1 = make_float2(0.f, 0.f);
    for (int j = s; j < e; j += 4) {
        uint2 e0 = __ldg(&g_edge[j]);
        uint2 e1 = (j + 1 < e) ? __ldg(&g_edge[j + 1]) : make_uint2(0u, 0u);
        uint2 e2 = (j + 2 < e) ? __ldg(&g_edge[j + 2]) : make_uint2(0u, 0u);
        uint2 e3 = (j + 3 < e) ? __ldg(&g_edge[j + 3]) : make_uint2(0u, 0u);
        uint2 g0 = __ldg(&x[(size_t)e0.x * 16 + l15]);
        uint2 g1 = __ldg(&x[(size_t)e1.x * 16 + l15]);
        uint2 g2 = __ldg(&x[(size_t)e2.x * 16 + l15]);
        uint2 g3 = __ldg(&x[(size_t)e3.x * 16 + l15]);
        float v0 = __uint_as_float(e0.y);
        float v1 = __uint_as_float(e1.y);
        float v2 = __uint_as_float(e2.y);
        float v3 = __uint_as_float(e3.y);
        float2 a, b;
        unpack_half4(g0, a, b);
        s0.x = fmaf(v0, a.x, s0.x); s0.y = fmaf(v0, a.y, s0.y);
        s1.x = fmaf(v0, b.x, s1.x); s1.y = fmaf(v0, b.y, s1.y);
        unpack_half4(g1, a, b);
        s0.x = fmaf(v1, a.x, s0.x); s0.y = fmaf(v1, a.y, s0.y);
        s1.x = fmaf(v1, b.x, s1.x); s1.y = fmaf(v1, b.y, s1.y);
        unpack_half4(g2, a, b);
        s0.x = fmaf(v2, a.x, s0.x); s0.y = fmaf(v2, a.y, s0.y);
        s1.x = fmaf(v2, b.x, s1.x); s1.y = fmaf(v2, b.y, s1.y);
        unpack_half4(g3, a, b);
        s0.x = fmaf(v3, a.x, s0.x); s0.y = fmaf(v3, a.y, s0.y);
        s1.x = fmaf(v3, b.x, s1.x); s1.y = fmaf(v3, b.y, s1.y);
    }
}

__global__ void spmm_mid(int layer) {
    int warp = (blockIdx.x * blockDim.x + threadIdx.x) >> 5;
    int lane = threadIdx.x & 31;
    int row  = warp * 2 + (lane >> 4);
    if (row >= NROWS) return;
    int l15 = lane & 15;
    const uint2* __restrict__ x = (layer == 0) ? g_A16 : g_B16;
    uint2*       __restrict__ y = (layer == 0) ? g_B16 : g_C16;
    float2 s0, s1;
    row_spmv(x, g_ptr[row], g_ptr[row + 1], l15, s0, s1);
    y[(size_t)row * 16 + l15] = pack_half4(s0, s1);
}

__global__ void spmm_final(float4* __restrict__ out) {
    int warp = (blockIdx.x * blockDim.x + threadIdx.x) >> 5;
    int lane = threadIdx.x & 31;
    int row  = warp * 2 + (lane >> 4);
    if (row >= NROWS) return;
    int l15 = lane & 15;
    float2 s0, s1;
    row_spmv(g_C16, g_ptr[row], g_ptr[row + 1], l15, s0, s1);
    size_t o = (size_t)row * 16 + l15;
    float4 a = g_A4[o];
    float2 b0, b1, c0, c1;
    unpack_half4(g_B16[o], b0, b1);
    unpack_half4(g_C16[o], c0, c1);
    int outrow = (row < NUP1) ? row : row + 1;
    out[(size_t)outrow * 16 + l15] =
        make_float4((a.x + b0.x + c0.x + s0.x) * 0.25f,
                    (a.y + b0.y + c0.y + s0.y) * 0.25f,
                    (a.z + b1.x + c1.x + s1.x) * 0.25f,
                    (a.w + b1.y + c1.y + s1.y) * 0.25f);
    if (row == 0)
        out[(size_t)NUP1 * 16 + l15] = make_float4(0.f, 0.f, 0.f, 0.f);
}

extern "C" void kernel_launch(void* const* d_in, const int* in_sizes, int n_in,
                              void* d_out, int out_size) {
    const float4* user4 = (const float4*)d_in[0];
    const float4* item4 = (const float4*)d_in[1];
    const int*    rows  = (const int*)d_in[2];
    const int*    cols  = (const int*)d_in[3];
    const float*  vals  = (const float*)d_in[4];
    float4*       out   = (float4*)d_out;

    const int nnz = in_sizes[2];
    const int TB = 256;

    const int gInit = (NF4 + TB - 1) / TB;
    const int gEdge = (nnz + TB - 1) / TB;
    const int nWarp = (NROWS + 1) / 2;
    const int gSpmm = (nWarp * 32 + TB - 1) / TB;

    init_kernel<<<gInit, TB>>>(user4, item4, rows, nnz);   // 0: init + hist
    scan_kernel<<<NB, SCAN_B>>>();                         // 1
    scatter_kernel<<<gEdge, TB>>>(rows, cols, vals, nnz);  // 2
    spmm_mid<<<gSpmm, TB>>>(0);                            // 3  <- ncu lands here
    spmm_mid<<<gSpmm, TB>>>(1);                            // 4
    spmm_final<<<gSpmm, TB>>>(out);                        // 5
}